// round 2
// baseline (speedup 1.0000x reference)
#include <cuda_runtime.h>
#include <stdint.h>

// Problem constants
#define NPLANES 32            // B*C = 2*16
#define NTEX    512
#define HT      64
#define WT      64
#define TEXELS  (NTEX*HT*WT)  // 2,097,152 texels; also plane stride in x
#define HO      1024
#define WO      1024
#define NPIX    (HO*WO)       // 1,048,576 output pixels per plane

// 256 MB transposed atlas: g_xt[texel][channel], channel innermost so one
// texel's 32 channels are one 128B line.
__device__ float g_xt[(size_t)TEXELS * NPLANES];

// ---------------------------------------------------------------------------
// Pass 1: transpose x [32 planes][TEXELS] -> g_xt [TEXELS][32 planes]
// Tile: 32 planes x 128 texels. 1024 threads = 32 warps.
//   Phase A: warp w loads plane w, 128 texels (4x coalesced 128B LDG).
//   Phase B: warp w writes 4 texels' channel blocks (coalesced 128B STG).
// smem pitch 129 -> column reads (lane*129 + t) are bank-conflict-free.
// ---------------------------------------------------------------------------
__global__ __launch_bounds__(1024) void transpose_kernel(const float* __restrict__ x) {
    __shared__ float tile[32][129];
    const int w    = threadIdx.x >> 5;
    const int lane = threadIdx.x & 31;
    const int tbase = blockIdx.x * 128;

    const float* src = x + (size_t)w * TEXELS + tbase;
    #pragma unroll
    for (int i = 0; i < 4; i++) {
        tile[w][i * 32 + lane] = src[i * 32 + lane];
    }
    __syncthreads();
    #pragma unroll
    for (int i = 0; i < 4; i++) {
        const int t = w + i * 32;                       // 0..127
        g_xt[(size_t)(tbase + t) * NPLANES + lane] = tile[lane][t];
    }
}

// ---------------------------------------------------------------------------
// Pass 2: warp-per-pixel bilinear gather.
// Block = 256 threads (8 warps) handles 64 contiguous pixels.
//   Phase 1: warp w, iter i -> pixel (w*8+i). All lanes broadcast-load
//            quad_idx / uv, compute the 4 corner texel bases; lane = channel
//            loads 4 coalesced 128B corner lines, computes bilinear, stores
//            to smem[pixel][channel] (pitch 33).
//   Phase 2: per plane p, write 64 contiguous output floats (coalesced).
// ---------------------------------------------------------------------------
__global__ __launch_bounds__(256) void sample_kernel(
    const int*    __restrict__ qidx,    // int32 (harness materializes int64 as int32)
    const float2* __restrict__ uv,
    float*        __restrict__ out) {

    __shared__ float s[64][33];
    const int w    = threadIdx.x >> 5;
    const int lane = threadIdx.x & 31;
    const int pixbase = blockIdx.x * 64;

    #pragma unroll
    for (int i = 0; i < 8; i++) {
        const int pl  = w * 8 + i;          // local pixel 0..63
        const int pix = pixbase + pl;

        int n = qidx[pix];
        n = min(max(n, 0), NTEX - 1);       // defensive: keep gather in-bounds
        const float2 t  = uv[pix];
        const float  u  = t.x * 63.0f;
        const float  v  = t.y * 63.0f;
        const float  x0f = floorf(u);
        const float  y0f = floorf(v);
        const float  wu  = u - x0f;
        const float  wv  = v - y0f;

        int x0 = (int)x0f; x0 = min(max(x0, 0), WT - 1);
        int y0 = (int)y0f; y0 = min(max(y0, 0), HT - 1);
        const int x1 = min(x0 + 1, WT - 1);
        const int y1 = min(y0 + 1, HT - 1);

        const int rb   = n * (HT * WT);
        const int r0   = rb + y0 * WT;
        const int r1   = rb + y1 * WT;

        const float g00 = g_xt[(size_t)(r0 + x0) * NPLANES + lane];
        const float g01 = g_xt[(size_t)(r0 + x1) * NPLANES + lane];
        const float g10 = g_xt[(size_t)(r1 + x0) * NPLANES + lane];
        const float g11 = g_xt[(size_t)(r1 + x1) * NPLANES + lane];

        const float top = fmaf(wu, g01 - g00, g00);
        const float bot = fmaf(wu, g11 - g10, g10);
        s[pl][lane] = fmaf(wv, bot - top, top);
    }

    __syncthreads();

    // Write: 32 planes / 8 warps = 4 planes per warp; 64 pixels per plane.
    #pragma unroll
    for (int j = 0; j < 4; j++) {
        const int p = w * 4 + j;
        float* o = out + (size_t)p * NPIX + pixbase;
        o[lane]      = s[lane][p];        // banks (lane+p)%32: conflict-free
        o[32 + lane] = s[32 + lane][p];
    }
}

extern "C" void kernel_launch(void* const* d_in, const int* in_sizes, int n_in,
                              void* d_out, int out_size) {
    const float*  x    = (const float*)d_in[0];
    const int*    qidx = (const int*)d_in[1];
    const float2* uv   = (const float2*)d_in[2];
    float*        out  = (float*)d_out;

    transpose_kernel<<<TEXELS / 128, 1024>>>(x);
    sample_kernel<<<NPIX / 64, 256>>>(qidx, uv, out);
}

// round 3
// speedup vs baseline: 1.2136x; 1.2136x over previous
#include <cuda_runtime.h>
#include <cuda_fp16.h>
#include <stdint.h>

// Problem constants
#define NPLANES 32            // B*C = 2*16
#define NTEX    512
#define HT      64
#define WT      64
#define TEXELS  (NTEX*HT*WT)  // 2,097,152 texels; plane stride in x
#define HO      1024
#define WO      1024
#define NPIX    (HO*WO)

// 128 MB transposed fp16 atlas: g_xt_h[texel][channel]; one texel's 32
// channels = one 64B half-line.
__device__ __half g_xt_h[(size_t)TEXELS * NPLANES];

// ---------------------------------------------------------------------------
// Pass 1: transpose + fp32->fp16. Tile: 32 planes x 128 texels, 1024 thr.
//  Phase A: warp w loads plane w, 128 texels via one LDG.128 per lane.
//  Phase B: warp w handles texel pairs; lanes 0-15 texel t (even), lanes
//           16-31 texel t+1 (odd). Each lane packs channels (2s,2s+1) into
//           half2 and stores 4B -> the warp's STG covers one contiguous
//           128B block (two 64B texel lines).
//  smem pitch 129: bank(tile[r][t]) = (r+t)%32; group A (t even) uses even
//  banks, group B (t odd) odd banks -> conflict-free LDS.
// ---------------------------------------------------------------------------
__global__ __launch_bounds__(1024) void transpose_kernel(const float* __restrict__ x) {
    __shared__ float tile[32][129];
    const int w    = threadIdx.x >> 5;
    const int lane = threadIdx.x & 31;
    const int tbase = blockIdx.x * 128;

    // Phase A: 128B vector load per lane
    const float4* src = (const float4*)(x + (size_t)w * TEXELS + tbase);
    const float4 v = src[lane];
    tile[w][lane * 4 + 0] = v.x;
    tile[w][lane * 4 + 1] = v.y;
    tile[w][lane * 4 + 2] = v.z;
    tile[w][lane * 4 + 3] = v.w;
    __syncthreads();

    // Phase B: 4 texels per warp, processed as 2 pairs
    const int g   = lane >> 4;        // texel-within-pair
    const int sub = lane & 15;        // channel pair index
    #pragma unroll
    for (int i = 0; i < 2; i++) {
        const int t = w * 4 + 2 * i + g;            // local texel 0..127
        const float v0 = tile[2 * sub][t];
        const float v1 = tile[2 * sub + 1][t];
        ((__half2*)g_xt_h)[(size_t)(tbase + t) * (NPLANES / 2) + sub] =
            __floats2half2_rn(v0, v1);
    }
}

// ---------------------------------------------------------------------------
// Pass 2: warp-per-pixel bilinear gather from fp16 atlas.
// Block = 256 threads (8 warps) -> 64 contiguous pixels; lane = channel.
// 4 coalesced 64B corner loads per pixel, fp32 math, smem-staged coalesced
// output writes.
// ---------------------------------------------------------------------------
__global__ __launch_bounds__(256) void sample_kernel(
    const int*    __restrict__ qidx,
    const float2* __restrict__ uv,
    float*        __restrict__ out) {

    __shared__ float s[64][33];
    const int w    = threadIdx.x >> 5;
    const int lane = threadIdx.x & 31;
    const int pixbase = blockIdx.x * 64;

    #pragma unroll
    for (int i = 0; i < 8; i++) {
        const int pl  = w * 8 + i;
        const int pix = pixbase + pl;

        int n = qidx[pix];
        n = min(max(n, 0), NTEX - 1);
        const float2 t  = uv[pix];
        const float  u  = t.x * 63.0f;
        const float  v  = t.y * 63.0f;
        const float  x0f = floorf(u);
        const float  y0f = floorf(v);
        const float  wu  = u - x0f;
        const float  wv  = v - y0f;

        int x0 = (int)x0f; x0 = min(max(x0, 0), WT - 1);
        int y0 = (int)y0f; y0 = min(max(y0, 0), HT - 1);
        const int x1 = min(x0 + 1, WT - 1);
        const int y1 = min(y0 + 1, HT - 1);

        const int rb = n * (HT * WT);
        const int r0 = rb + y0 * WT;
        const int r1 = rb + y1 * WT;

        const float g00 = __half2float(g_xt_h[(size_t)(r0 + x0) * NPLANES + lane]);
        const float g01 = __half2float(g_xt_h[(size_t)(r0 + x1) * NPLANES + lane]);
        const float g10 = __half2float(g_xt_h[(size_t)(r1 + x0) * NPLANES + lane]);
        const float g11 = __half2float(g_xt_h[(size_t)(r1 + x1) * NPLANES + lane]);

        const float top = fmaf(wu, g01 - g00, g00);
        const float bot = fmaf(wu, g11 - g10, g10);
        s[pl][lane] = fmaf(wv, bot - top, top);
    }

    __syncthreads();

    #pragma unroll
    for (int j = 0; j < 4; j++) {
        const int p = w * 4 + j;
        float* o = out + (size_t)p * NPIX + pixbase;
        o[lane]      = s[lane][p];
        o[32 + lane] = s[32 + lane][p];
    }
}

extern "C" void kernel_launch(void* const* d_in, const int* in_sizes, int n_in,
                              void* d_out, int out_size) {
    const float*  x    = (const float*)d_in[0];
    const int*    qidx = (const int*)d_in[1];
    const float2* uv   = (const float2*)d_in[2];
    float*        out  = (float*)d_out;

    transpose_kernel<<<TEXELS / 128, 1024>>>(x);
    sample_kernel<<<NPIX / 64, 256>>>(qidx, uv, out);
}

// round 4
// speedup vs baseline: 1.3474x; 1.1103x over previous
#include <cuda_runtime.h>
#include <cuda_fp16.h>
#include <stdint.h>

// Problem constants
#define NPLANES 32            // B*C = 2*16
#define NTEX    512
#define HT      64
#define WT      64
#define TEXELS  (NTEX*HT*WT)  // 2,097,152 texels; plane stride in x
#define HO      1024
#define WO      1024
#define NPIX    (HO*WO)

// 128 MB transposed fp16 atlas: g_xt_h[texel][channel]; one texel's 32
// channels = one 64B half-line (16 half2).
__device__ __half g_xt_h[(size_t)TEXELS * NPLANES];

// ---------------------------------------------------------------------------
// Pass 1: transpose + fp32->fp16 (unchanged from R3; ~88us, near DRAM cap).
// ---------------------------------------------------------------------------
__global__ __launch_bounds__(1024) void transpose_kernel(const float* __restrict__ x) {
    __shared__ float tile[32][129];
    const int w    = threadIdx.x >> 5;
    const int lane = threadIdx.x & 31;
    const int tbase = blockIdx.x * 128;

    const float4* src = (const float4*)(x + (size_t)w * TEXELS + tbase);
    const float4 v = src[lane];
    tile[w][lane * 4 + 0] = v.x;
    tile[w][lane * 4 + 1] = v.y;
    tile[w][lane * 4 + 2] = v.z;
    tile[w][lane * 4 + 3] = v.w;
    __syncthreads();

    const int g   = lane >> 4;
    const int sub = lane & 15;
    #pragma unroll
    for (int i = 0; i < 2; i++) {
        const int t = w * 4 + 2 * i + g;
        const float v0 = tile[2 * sub][t];
        const float v1 = tile[2 * sub + 1][t];
        ((__half2*)g_xt_h)[(size_t)(tbase + t) * (NPLANES / 2) + sub] =
            __floats2half2_rn(v0, v1);
    }
}

// ---------------------------------------------------------------------------
// Pass 2: 2 pixels per warp per iteration via half2 lanes.
//  lane < 16 -> pixel A, lane >= 16 -> pixel B; j = lane&15 = channel pair.
//  Each corner LDG.32 (half2) serves both pixels -> 2 LDG issues/pixel.
//  fp32 bilinear on both channels, two conflict-free STS.32 into pitch-33
//  staging tile, then coalesced per-plane output via __stwt (no L2 alloc,
//  keeps the atlas resident in L2).
// ---------------------------------------------------------------------------
__global__ __launch_bounds__(256) void sample_kernel(
    const int*    __restrict__ qidx,
    const float2* __restrict__ uv,
    float*        __restrict__ out) {

    __shared__ float s[64][33];
    const int w    = threadIdx.x >> 5;
    const int lane = threadIdx.x & 31;
    const int half = lane >> 4;         // which pixel of the pair
    const int j    = lane & 15;         // channel-pair index
    const int pixbase = blockIdx.x * 64;

    const __half2* atlas = (const __half2*)g_xt_h;

    #pragma unroll
    for (int i = 0; i < 4; i++) {
        const int pl  = w * 8 + i * 2 + half;   // local pixel 0..63
        const int pix = pixbase + pl;

        int n = __ldcs(&qidx[pix]);
        n = min(max(n, 0), NTEX - 1);
        const float2 t = __ldcs(&uv[pix]);
        const float  u  = t.x * 63.0f;
        const float  v  = t.y * 63.0f;
        const float  x0f = floorf(u);
        const float  y0f = floorf(v);
        const float  wu  = u - x0f;
        const float  wv  = v - y0f;

        int x0 = (int)x0f; x0 = min(max(x0, 0), WT - 1);
        int y0 = (int)y0f; y0 = min(max(y0, 0), HT - 1);
        const int x1 = min(x0 + 1, WT - 1);
        const int y1 = min(y0 + 1, HT - 1);

        const int rb = n * (HT * WT);
        const int r0 = rb + y0 * WT;
        const int r1 = rb + y1 * WT;

        const float2 g00 = __half22float2(atlas[(size_t)(r0 + x0) * 16 + j]);
        const float2 g01 = __half22float2(atlas[(size_t)(r0 + x1) * 16 + j]);
        const float2 g10 = __half22float2(atlas[(size_t)(r1 + x0) * 16 + j]);
        const float2 g11 = __half22float2(atlas[(size_t)(r1 + x1) * 16 + j]);

        const float topx = fmaf(wu, g01.x - g00.x, g00.x);
        const float botx = fmaf(wu, g11.x - g10.x, g10.x);
        const float topy = fmaf(wu, g01.y - g00.y, g00.y);
        const float boty = fmaf(wu, g11.y - g10.y, g10.y);

        s[pl][2 * j]     = fmaf(wv, botx - topx, topx);
        s[pl][2 * j + 1] = fmaf(wv, boty - topy, topy);
    }

    __syncthreads();

    // 32 planes / 8 warps = 4 planes per warp; 64 contiguous pixels per plane.
    #pragma unroll
    for (int jj = 0; jj < 4; jj++) {
        const int p = w * 4 + jj;
        float* o = out + (size_t)p * NPIX + pixbase;
        __stwt(&o[lane],      s[lane][p]);
        __stwt(&o[32 + lane], s[32 + lane][p]);
    }
}

extern "C" void kernel_launch(void* const* d_in, const int* in_sizes, int n_in,
                              void* d_out, int out_size) {
    const float*  x    = (const float*)d_in[0];
    const int*    qidx = (const int*)d_in[1];
    const float2* uv   = (const float2*)d_in[2];
    float*        out  = (float*)d_out;

    transpose_kernel<<<TEXELS / 128, 1024>>>(x);
    sample_kernel<<<NPIX / 64, 256>>>(qidx, uv, out);
}

// round 5
// speedup vs baseline: 1.5255x; 1.1322x over previous
#include <cuda_runtime.h>
#include <cuda_fp16.h>
#include <stdint.h>

// Problem constants
#define NPLANES 32            // B*C = 2*16
#define NTEX    512
#define HT      64
#define WT      64
#define TEXELS  (NTEX*HT*WT)  // 2,097,152 texels; plane stride in x
#define HO      1024
#define WO      1024
#define NPIX    (HO*WO)

#define TILE_T  256           // texels per transpose tile

// 128 MB transposed fp16 atlas: g_xt_h[texel][channel]; one texel's 32
// channels = one 64B half-line (16 half2).
__device__ __half g_xt_h[(size_t)TEXELS * NPLANES];

// ---------------------------------------------------------------------------
// Pass 1 v2: transpose + fp32->fp16, 32 planes x 256 texels per block.
//  Phase A: warp w = plane w; 2 independent LDG.128 per lane (MLP=2),
//           scalar STS into pitch-257 tile (contiguous, conflict-free).
//  Phase B: lane = tq*8 + c (tq: texel-in-group, c: channel quad).
//           4 LDS.32 tile[4c+k][t] -> banks (4c+k+t)%32, all 32 distinct.
//           Pack 2x half2 -> STG.64; warp writes 4 texels x 64B = 256B
//           contiguous per iteration.
// ---------------------------------------------------------------------------
__global__ __launch_bounds__(1024) void transpose_kernel(const float* __restrict__ x) {
    __shared__ float tile[32][TILE_T + 1];   // pitch 257 -> bank (r+t)%32
    const int w    = threadIdx.x >> 5;
    const int lane = threadIdx.x & 31;
    const int tbase = blockIdx.x * TILE_T;

    // Phase A: plane w, 256 texels, 2x LDG.128 per lane
    const float4* src4 = (const float4*)(x + (size_t)w * TEXELS + tbase);
    const float4 a = src4[lane];
    const float4 b = src4[32 + lane];
    {
        const int t0 = lane * 4;
        tile[w][t0 + 0] = a.x; tile[w][t0 + 1] = a.y;
        tile[w][t0 + 2] = a.z; tile[w][t0 + 3] = a.w;
        const int t1 = (32 + lane) * 4;
        tile[w][t1 + 0] = b.x; tile[w][t1 + 1] = b.y;
        tile[w][t1 + 2] = b.z; tile[w][t1 + 3] = b.w;
    }
    __syncthreads();

    // Phase B: warp w covers texels [w*8, w*8+8); 2 iterations of 4 texels.
    const int tq = lane >> 3;          // 0..3 texel within group
    const int c  = lane & 7;           // 0..7 channel quad (channels 4c..4c+3)
    #pragma unroll
    for (int j = 0; j < 2; j++) {
        const int t = w * 8 + j * 4 + tq;        // local texel
        const float v0 = tile[4 * c + 0][t];
        const float v1 = tile[4 * c + 1][t];
        const float v2 = tile[4 * c + 2][t];
        const float v3 = tile[4 * c + 3][t];
        const __half2 h0 = __floats2half2_rn(v0, v1);
        const __half2 h1 = __floats2half2_rn(v2, v3);
        uint2 pk;
        pk.x = *(const unsigned int*)&h0;
        pk.y = *(const unsigned int*)&h1;
        *(uint2*)(g_xt_h + (size_t)(tbase + t) * NPLANES + 4 * c) = pk;
    }
}

// ---------------------------------------------------------------------------
// Pass 2 (unchanged from R4): 2 pixels per warp per iteration via half2
// lanes; 2 LDG issues/pixel; __stwt coalesced output.
// ---------------------------------------------------------------------------
__global__ __launch_bounds__(256) void sample_kernel(
    const int*    __restrict__ qidx,
    const float2* __restrict__ uv,
    float*        __restrict__ out) {

    __shared__ float s[64][33];
    const int w    = threadIdx.x >> 5;
    const int lane = threadIdx.x & 31;
    const int half = lane >> 4;
    const int j    = lane & 15;
    const int pixbase = blockIdx.x * 64;

    const __half2* atlas = (const __half2*)g_xt_h;

    #pragma unroll
    for (int i = 0; i < 4; i++) {
        const int pl  = w * 8 + i * 2 + half;
        const int pix = pixbase + pl;

        int n = __ldcs(&qidx[pix]);
        n = min(max(n, 0), NTEX - 1);
        const float2 t = __ldcs(&uv[pix]);
        const float  u  = t.x * 63.0f;
        const float  v  = t.y * 63.0f;
        const float  x0f = floorf(u);
        const float  y0f = floorf(v);
        const float  wu  = u - x0f;
        const float  wv  = v - y0f;

        int x0 = (int)x0f; x0 = min(max(x0, 0), WT - 1);
        int y0 = (int)y0f; y0 = min(max(y0, 0), HT - 1);
        const int x1 = min(x0 + 1, WT - 1);
        const int y1 = min(y0 + 1, HT - 1);

        const int rb = n * (HT * WT);
        const int r0 = rb + y0 * WT;
        const int r1 = rb + y1 * WT;

        const float2 g00 = __half22float2(atlas[(size_t)(r0 + x0) * 16 + j]);
        const float2 g01 = __half22float2(atlas[(size_t)(r0 + x1) * 16 + j]);
        const float2 g10 = __half22float2(atlas[(size_t)(r1 + x0) * 16 + j]);
        const float2 g11 = __half22float2(atlas[(size_t)(r1 + x1) * 16 + j]);

        const float topx = fmaf(wu, g01.x - g00.x, g00.x);
        const float botx = fmaf(wu, g11.x - g10.x, g10.x);
        const float topy = fmaf(wu, g01.y - g00.y, g00.y);
        const float boty = fmaf(wu, g11.y - g10.y, g10.y);

        s[pl][2 * j]     = fmaf(wv, botx - topx, topx);
        s[pl][2 * j + 1] = fmaf(wv, boty - topy, topy);
    }

    __syncthreads();

    #pragma unroll
    for (int jj = 0; jj < 4; jj++) {
        const int p = w * 4 + jj;
        float* o = out + (size_t)p * NPIX + pixbase;
        __stwt(&o[lane],      s[lane][p]);
        __stwt(&o[32 + lane], s[32 + lane][p]);
    }
}

extern "C" void kernel_launch(void* const* d_in, const int* in_sizes, int n_in,
                              void* d_out, int out_size) {
    const float*  x    = (const float*)d_in[0];
    const int*    qidx = (const int*)d_in[1];
    const float2* uv   = (const float2*)d_in[2];
    float*        out  = (float*)d_out;

    transpose_kernel<<<TEXELS / TILE_T, 1024>>>(x);
    sample_kernel<<<NPIX / 64, 256>>>(qidx, uv, out);
}